// round 16
// baseline (speedup 1.0000x reference)
#include <cuda_runtime.h>
#include <cuda_fp16.h>
#include <math.h>
#include <stdint.h>

#define N_NODES 20000
#define B_GR    128
#define FIN     768
#define RAWF    5000
#define HDIM    256
#define LDK     40     // padded SMEM k-stride (fp16 elems)
#define BM      144    // rows per CTA: ceil(20000/144)=139 <= 148 SMs -> single wave
#define NTG     384    // 12 warps: 3m x 4n
#define EMAX    360000

// ---------------- device scratch ----------------
__device__ float g_h  [N_NODES * HDIM];
__device__ float g_xa [N_NODES * HDIM];
__device__ float g_xb [N_NODES * HDIM];
__device__ float g_dinv_g[N_NODES];
__device__ float g_dinv_r[N_NODES];
__device__ int   g_deg_g [N_NODES];
__device__ int   g_deg_r [N_NODES];
__device__ int   g_start [B_GR];
__device__ int   g_end   [B_GR];
__device__ float g_cat [B_GR * 2 * RAWF];
__device__ float g_h2  [B_GR * 512];
__device__ float g_f5  [B_GR * 5 * HDIM];
__device__ uint16_t g_wT[256 * RAWF];      // W^T fp16 [256, K]
// CSR structures (per edge set): rowptr + interleaved (src, norm) pairs
__device__ int   g_rowg[N_NODES + 1];
__device__ int   g_rowr[N_NODES + 1];
__device__ int   g_curg[N_NODES];
__device__ int   g_curr[N_NODES];
__device__ int2  g_edgg[EMAX];
__device__ int2  g_edgr[EMAX];

// ================= helpers =================
__device__ __forceinline__ uint32_t smem_u32(const void* p) {
    uint32_t a;
    asm("{ .reg .u64 t; cvta.to.shared.u64 t, %1; cvt.u32.u64 %0, t; }" : "=r"(a) : "l"(p));
    return a;
}
__device__ __forceinline__ void ldm_x4(uint32_t* r, uint32_t addr) {
    asm volatile("ldmatrix.sync.aligned.m8n8.x4.shared.b16 {%0,%1,%2,%3}, [%4];"
        : "=r"(r[0]), "=r"(r[1]), "=r"(r[2]), "=r"(r[3]) : "r"(addr));
}
__device__ __forceinline__ void mma16816(float* d, const uint32_t* a, const uint32_t* b) {
    asm volatile("mma.sync.aligned.m16n8k16.row.col.f32.f16.f16.f32 "
        "{%0,%1,%2,%3}, {%4,%5,%6,%7}, {%8,%9}, {%0,%1,%2,%3};"
        : "+f"(d[0]), "+f"(d[1]), "+f"(d[2]), "+f"(d[3])
        : "r"(a[0]), "r"(a[1]), "r"(a[2]), "r"(a[3]), "r"(b[0]), "r"(b[1]));
}
template<int N>
__device__ __forceinline__ void cp_wait() {
    asm volatile("cp.async.wait_group %0;" :: "n"(N) : "memory");
}
__device__ __forceinline__ void cp_commit() {
    asm volatile("cp.async.commit_group;" ::: "memory");
}
__device__ __forceinline__ void cp_async16(uint32_t dst, const void* src, int srcsize) {
    asm volatile("cp.async.cg.shared.global [%0], [%1], 16, %2;"
        :: "r"(dst), "l"(src), "r"(srcsize) : "memory");
}

// SMEM layout: A bufs [0,46080), B bufs [46080,87040), sbatch [87040,87616), swarp [87616,92224)
#define SEG_SBATCH 87040
#define SEG_SWARP  87616
#define MMA_SMEM   92224

// ======== pipelined mma.sync GEMM: H[M,256] = T(A)[M,K] @ W[K,256] ========
// T(A) = relu(A + abias) if abias != null, else A  (fused prev-layer bias+relu)
// A split hi/lo fp16, W fp16 -> 2 MMA passes.
// SEGSUM: additionally accumulates per-graph column sums of RAW A into segglob
// (ld = 2*RAWF), using batchArr (sorted). CTA spans <= 2 graphs.
template<bool SEGSUM>
__global__ void __launch_bounds__(NTG) gcn_gemm_mma(
    const float* __restrict__ A, const uint16_t* __restrict__ BT,
    float* __restrict__ H, const float* __restrict__ abias,
    const int* __restrict__ batchArr, float* __restrict__ segglob, int M, int K)
{
    extern __shared__ char smem[];
    const int tid  = threadIdx.x;
    const int wid  = tid >> 5;
    const int lane = tid & 31;
    const int wm   = wid >> 2;
    const int wn   = wid & 3;
    const int rowBase = blockIdx.x * BM;
    const uint32_t sb = smem_u32(smem);
    int* sbatch  = (int*)(smem + SEG_SBATCH);
    float* swarp = (float*)(smem + SEG_SWARP);   // [18][2][32]

    const int qa = lane >> 3, ia = lane & 7;
    const int aRowLane = ia + ((qa & 1) << 3);
    const int aKLane   = (qa >> 1) << 3;
    const int bRowLane = ia + ((qa >> 1) << 3);
    const int bKLane   = (qa & 1) << 3;

    int gmin = 0;
    if (SEGSUM) {
        if (tid < BM) {
            int r = rowBase + tid;
            sbatch[tid] = batchArr[r < M ? r : (M - 1)];
        }
        __syncthreads();
        gmin = sbatch[0];
    }

    float acc[3][8][4];
#pragma unroll
    for (int i = 0; i < 3; i++)
#pragma unroll
        for (int j = 0; j < 8; j++)
#pragma unroll
            for (int l = 0; l < 4; l++) acc[i][j][l] = 0.f;

    const int nCh = (K + 31) / 32;
    float va[2][8];

#define LDG_A(kg_) do { \
    _Pragma("unroll") \
    for (int sl = 0; sl < 2; sl++) { \
        int slot = tid + sl * NTG; \
        if (slot >= 576) break; \
        int row = slot >> 2, seg = slot & 3; \
        int grow = rowBase + row, gk = (kg_) + seg * 8; \
        _Pragma("unroll") \
        for (int j = 0; j < 8; j++) va[sl][j] = 0.f; \
        if (grow < M && gk + 8 <= K) { \
            float4 v0 = *(const float4*)(A + (size_t)grow * K + gk); \
            float4 v1 = *(const float4*)(A + (size_t)grow * K + gk + 4); \
            va[sl][0]=v0.x; va[sl][1]=v0.y; va[sl][2]=v0.z; va[sl][3]=v0.w; \
            va[sl][4]=v1.x; va[sl][5]=v1.y; va[sl][6]=v1.z; va[sl][7]=v1.w; \
        } \
    } } while (0)

#define CVT_STS_A(kg_, p_) do { \
    _Pragma("unroll") \
    for (int sl = 0; sl < 2; sl++) { \
        int slot = tid + sl * NTG; \
        if (slot >= 576) break; \
        int row = slot >> 2, seg = slot & 3; \
        int grow = rowBase + row, gk = (kg_) + seg * 8; \
        float v[8]; \
        _Pragma("unroll") \
        for (int j = 0; j < 8; j++) v[j] = va[sl][j]; \
        if (SEGSUM) { \
            int rg = row & ~7; \
            int g0 = sbatch[rg], g7 = sbatch[rg + 7]; \
            int myb = sbatch[row]; \
            int b0 = g0 - gmin, b7 = g7 - gmin; \
            int wslot = (sl == 0) ? (tid >> 5) : (12 + (tid >> 5)); \
            _Pragma("unroll") \
            for (int j = 0; j < 8; j++) { \
                float x  = v[j]; \
                float x0 = (myb == g0) ? x : 0.f; \
                float x1 = x - x0; \
                _Pragma("unroll") \
                for (int sft = 4; sft < 32; sft <<= 1) { \
                    x0 += __shfl_xor_sync(0xFFFFFFFFu, x0, sft); \
                    x1 += __shfl_xor_sync(0xFFFFFFFFu, x1, sft); \
                } \
                if (lane < 4) { \
                    float w0 = (b0 == 0 ? x0 : 0.f) + (b7 == 0 ? x1 : 0.f); \
                    float w1 = (b0 == 1 ? x0 : 0.f) + (b7 == 1 ? x1 : 0.f); \
                    swarp[(wslot * 2 + 0) * 32 + lane * 8 + j] = w0; \
                    swarp[(wslot * 2 + 1) * 32 + lane * 8 + j] = w1; \
                } \
            } \
        } \
        if (abias && grow < M && gk + 8 <= K) { \
            _Pragma("unroll") \
            for (int j = 0; j < 8; j++) v[j] = fmaxf(v[j] + abias[gk + j], 0.f); \
        } \
        uint16_t hi[8], lo[8]; \
        _Pragma("unroll") \
        for (int j = 0; j < 8; j++) { \
            __half hh = __float2half_rn(v[j]); \
            float  rs = v[j] - __half2float(hh); \
            hi[j] = __half_as_ushort(hh); \
            lo[j] = __half_as_ushort(__float2half_rn(rs)); \
        } \
        int off = (row * LDK + seg * 8) * 2; \
        *(uint4*)(smem + (p_) * 23040 + off)         = *(uint4*)hi; \
        *(uint4*)(smem + (p_) * 23040 + 11520 + off) = *(uint4*)lo; \
    } } while (0)

#define CPA_B(kg_, p_) do { \
    _Pragma("unroll") \
    for (int s = tid; s < 1024; s += NTG) { \
        int n = s >> 2, seg = s & 3; \
        int gk = (kg_) + seg * 8; \
        uint32_t dst = sb + 46080 + (p_) * 20480 + (uint32_t)(n * LDK + seg * 8) * 2; \
        cp_async16(dst, BT + (size_t)n * K + gk, (gk + 8 <= K) ? 16 : 0); \
    } } while (0)

    LDG_A(0);
    CPA_B(0, 0);
    cp_commit();
    CVT_STS_A(0, 0);
    int kflush = 0;

    for (int c = 0; c < nCh; c++) {
        const int p = c & 1, q = p ^ 1;
        const int kgN = (c + 1) * 32;
        __syncthreads();
        // flush segment sums of the chunk whose CVT completed before this sync
        if (SEGSUM && tid < 64) {
            int bk = tid >> 5, col = tid & 31;
            float s = 0.f;
#pragma unroll
            for (int w = 0; w < 18; w++) s += swarp[(w * 2 + bk) * 32 + col];
            int gcol = kflush + col;
            int gb = gmin + bk;
            if (s != 0.f && gcol < K && gb < B_GR)
                atomicAdd(segglob + (size_t)gb * (2 * RAWF) + gcol, s);
        }
        if (c + 1 < nCh) {
            LDG_A(kgN);
            CPA_B(kgN, q);
            cp_commit();
            cp_wait<1>();
        } else {
            cp_wait<0>();
        }
        __syncthreads();

        const uint32_t aHiB = sb + p * 23040;
        const uint32_t aLoB = aHiB + 11520;
        const uint32_t bB   = sb + 46080 + p * 20480;
#pragma unroll
        for (int ks = 0; ks < 2; ks++) {
            uint32_t ahi[3][4], alo[3][4];
#pragma unroll
            for (int mf = 0; mf < 3; mf++) {
                uint32_t off = (uint32_t)(((wm * 48 + mf * 16 + aRowLane) * LDK
                                          + ks * 16 + aKLane) * 2);
                ldm_x4(ahi[mf], aHiB + off);
                ldm_x4(alo[mf], aLoB + off);
            }
#pragma unroll
            for (int ng = 0; ng < 4; ng++) {
                uint32_t offB = (uint32_t)(((wn * 64 + ng * 16 + bRowLane) * LDK
                                           + ks * 16 + bKLane) * 2);
                uint32_t b[4];
                ldm_x4(b, bB + offB);
#pragma unroll
                for (int mf = 0; mf < 3; mf++) {
                    float* d0 = acc[mf][2 * ng];
                    float* d1 = acc[mf][2 * ng + 1];
                    mma16816(d0, ahi[mf], b + 0);
                    mma16816(d0, alo[mf], b + 0);
                    mma16816(d1, ahi[mf], b + 2);
                    mma16816(d1, alo[mf], b + 2);
                }
            }
        }
        if (c + 1 < nCh) { CVT_STS_A(kgN, q); kflush = kgN; }
    }

    // epilogue: write H only (self-loop handled by gather kernel)
#pragma unroll
    for (int mf = 0; mf < 3; mf++) {
        int rb = rowBase + wm * 48 + mf * 16 + (lane >> 2);
#pragma unroll
        for (int rr = 0; rr < 2; rr++) {
            int row = rb + rr * 8;
            if (row >= M) continue;
            float* Hp = H + (size_t)row * 256 + wn * 64 + (lane & 3) * 2;
#pragma unroll
            for (int g = 0; g < 8; g++)
                *(float2*)(Hp + g * 8) =
                    make_float2(acc[mf][g][rr * 2 + 0], acc[mf][g][rr * 2 + 1]);
        }
    }
#undef LDG_A
#undef CVT_STS_A
#undef CPA_B
}

// ---- W[K,256] -> W^T fp16 [256,K] ----
__global__ void wconv(const float* __restrict__ W, int K, uint16_t* __restrict__ wT)
{
    int idx = blockIdx.x * blockDim.x + threadIdx.x;
    if (idx >= K * 256) return;
    int k = idx >> 8, n = idx & 255;
    wT[(size_t)n * K + k] = __half_as_ushort(__float2half_rn(W[(size_t)k * 256 + n]));
}

// ---------------- graph preprocessing ----------------
__global__ void zero_f(float* p, int n) {
    for (int i = blockIdx.x * blockDim.x + threadIdx.x; i < n; i += gridDim.x * blockDim.x)
        p[i] = 0.f;
}
__global__ void zero_i(int* p, int n) {
    for (int i = blockIdx.x * blockDim.x + threadIdx.x; i < n; i += gridDim.x * blockDim.x)
        p[i] = 0;
}
__global__ void init_bounds(int* start, int* end) {
    int b = threadIdx.x;
    if (b < B_GR) { start[b] = N_NODES; end[b] = 0; }
}
__global__ void bounds_kernel(const int* __restrict__ batch, int* start, int* end, int n) {
    int i = blockIdx.x * blockDim.x + threadIdx.x;
    if (i >= n) return;
    int b = batch[i];
    atomicMin(&start[b], i);
    atomicMax(&end[b], i + 1);
}
__global__ void deg_kernel(const int* __restrict__ dst, int* deg, int E) {
    int e = blockIdx.x * blockDim.x + threadIdx.x;
    if (e < E) atomicAdd(&deg[dst[e]], 1);
}
__global__ void dinv_kernel(const int* __restrict__ deg, float* dinv, int n) {
    int i = blockIdx.x * blockDim.x + threadIdx.x;
    if (i < n) dinv[i] = rsqrtf((float)(deg[i] + 1));   // +1 self loop
}
// one-pass exclusive scan: 1024 threads x 20 contiguous elements each
__global__ void scan_kernel(const int* __restrict__ deg, int* __restrict__ rowptr,
                            int* __restrict__ cursor, int n)
{
    __shared__ int buf[1024];
    const int tid = threadIdx.x;
    const int base = tid * 20;
    int local[20];
    int s = 0;
#pragma unroll
    for (int i = 0; i < 20; i++) {
        int idx = base + i;
        int v = (idx < n) ? deg[idx] : 0;
        local[i] = s;
        s += v;
    }
    buf[tid] = s;
    __syncthreads();
#pragma unroll
    for (int st = 1; st < 1024; st <<= 1) {
        int t = (tid >= st) ? buf[tid - st] : 0;
        __syncthreads();
        buf[tid] += t;
        __syncthreads();
    }
    int excl = (tid > 0) ? buf[tid - 1] : 0;
#pragma unroll
    for (int i = 0; i < 20; i++) {
        int idx = base + i;
        if (idx < n) {
            int e = excl + local[i];
            rowptr[idx] = e;
            cursor[idx] = e;
        }
    }
    if (tid == 1023) rowptr[n] = buf[1023];
}
// fill CSR: interleaved (src, norm) sorted by dst
__global__ void csr_fill(const int* __restrict__ src, const int* __restrict__ dst,
                         const float* __restrict__ dinv, int* __restrict__ cursor,
                         int2* __restrict__ edg, int E)
{
    int e = blockIdx.x * blockDim.x + threadIdx.x;
    if (e >= E) return;
    int s = src[e], d = dst[e];
    int pos = atomicAdd(&cursor[d], 1);
    edg[pos] = make_int2(s, __float_as_int(dinv[s] * dinv[d]));
}

// ---- CSR gather: X[d,:] = dinv[d]^2 * H[d,:] + sum_{e: dst=d} norm[e] * H[src[e],:] ----
// 64 threads per node (float4 per thread), 4 nodes per 256-thread block, unroll x4
__global__ void __launch_bounds__(256) gcn_gather(
    const float4* __restrict__ H4, const int* __restrict__ rowptr,
    const int2* __restrict__ edg, const float* __restrict__ dinv,
    float4* __restrict__ X4)
{
    int node = blockIdx.x * 4 + (threadIdx.x >> 6);
    int f4 = threadIdx.x & 63;
    if (node >= N_NODES) return;
    int s0 = rowptr[node], s1 = rowptr[node + 1];
    float dv = dinv[node];
    float dv2 = dv * dv;
    float4 h = H4[(size_t)node * 64 + f4];
    float4 acc = make_float4(dv2 * h.x, dv2 * h.y, dv2 * h.z, dv2 * h.w);
    int j = s0;
    for (; j + 4 <= s1; j += 4) {
        int2 e0 = edg[j], e1 = edg[j + 1], e2 = edg[j + 2], e3 = edg[j + 3];
        float4 v0 = H4[(size_t)e0.x * 64 + f4];
        float4 v1 = H4[(size_t)e1.x * 64 + f4];
        float4 v2 = H4[(size_t)e2.x * 64 + f4];
        float4 v3 = H4[(size_t)e3.x * 64 + f4];
        float n0 = __int_as_float(e0.y), n1 = __int_as_float(e1.y);
        float n2 = __int_as_float(e2.y), n3 = __int_as_float(e3.y);
        acc.x += n0 * v0.x + n1 * v1.x + n2 * v2.x + n3 * v3.x;
        acc.y += n0 * v0.y + n1 * v1.y + n2 * v2.y + n3 * v3.y;
        acc.z += n0 * v0.z + n1 * v1.z + n2 * v2.z + n3 * v3.z;
        acc.w += n0 * v0.w + n1 * v1.w + n2 * v2.w + n3 * v3.w;
    }
    for (; j < s1; j++) {
        int2 e = edg[j];
        float nv = __int_as_float(e.y);
        float4 v = H4[(size_t)e.x * 64 + f4];
        acc.x += nv * v.x; acc.y += nv * v.y;
        acc.z += nv * v.z; acc.w += nv * v.w;
    }
    X4[(size_t)node * 64 + f4] = acc;
}

// ---------------- fused bias+relu pooling ----------------
__global__ void pool_max_br(const float* __restrict__ x, const float* __restrict__ bias,
                            const int* __restrict__ start, const int* __restrict__ end,
                            float* __restrict__ out, int ldo)
{
    int f = threadIdx.x;
    int b = blockIdx.x;
    int s = start[b], e = end[b];
    float bv = bias[f];
    float m = -INFINITY;
    for (int r = s; r < e; r++) m = fmaxf(m, fmaxf(x[(size_t)r * HDIM + f] + bv, 0.f));
    out[(size_t)b * ldo + f] = m;
}
__global__ void pool_mean_br(const float* __restrict__ x, const float* __restrict__ bias,
                             const int* __restrict__ start, const int* __restrict__ end,
                             float* __restrict__ out, int ldo)
{
    int f = threadIdx.x;
    int b = blockIdx.x;
    int s = start[b], e = end[b];
    float bv = bias[f];
    float sum = 0.f;
    for (int r = s; r < e; r++) sum += fmaxf(x[(size_t)r * HDIM + f] + bv, 0.f);
    int cnt = e - s; if (cnt < 1) cnt = 1;
    out[(size_t)b * ldo + f] = sum / (float)cnt;
}
// divide fused segment sums by counts (mean half of cat)
__global__ void mean_div(float* __restrict__ cat, const int* __restrict__ start,
                         const int* __restrict__ end)
{
    int f = blockIdx.x * blockDim.x + threadIdx.x;
    int b = blockIdx.y;
    if (f >= RAWF) return;
    int c = end[b] - start[b]; if (c < 1) c = 1;
    cat[(size_t)b * 2 * RAWF + f] *= (1.f / (float)c);
}
__global__ void gather_root(const float* __restrict__ x, const int* __restrict__ root,
                            float* __restrict__ out, int ldo)
{
    int f = blockIdx.x * blockDim.x + threadIdx.x;
    int b = blockIdx.y;
    if (f >= RAWF) return;
    out[(size_t)b * ldo + f] = x[(size_t)root[b] * RAWF + f];
}
__global__ void prelu_bias(const float* __restrict__ in, const float* __restrict__ bias,
                           const float* __restrict__ a_ptr, float* __restrict__ out,
                           int rows, int F, int ldo)
{
    int idx = blockIdx.x * blockDim.x + threadIdx.x;
    if (idx >= rows * F) return;
    int r = idx / F, f = idx - r * F;
    float a = *a_ptr;
    float v = in[idx] + bias[f];
    out[(size_t)r * ldo + f] = v >= 0.f ? v : a * v;
}

// ---------------- FFMA GEMM (branch-2 only) ----------------
template <bool ATOMIC>
__global__ void sgemm128(const float* __restrict__ A, const float* __restrict__ B,
                         float* __restrict__ C, int M, int N, int K, int ldc, int kChunk)
{
    __shared__ float As[8][128];
    __shared__ float Bs[8][128];
    const int tid = threadIdx.x;
    const int br = blockIdx.y * 128;
    const int bc = blockIdx.x * 128;
    int k0 = blockIdx.z * kChunk;
    int k1 = k0 + kChunk; if (k1 > K) k1 = K;

    const int tRow = (tid >> 4) << 3;
    const int tCol = (tid & 15) << 3;

    float acc[8][8];
#pragma unroll
    for (int i = 0; i < 8; i++)
#pragma unroll
        for (int j = 0; j < 8; j++) acc[i][j] = 0.f;

    const int aRow = tid >> 1;
    const int aCol = (tid & 1) << 2;
    const int bRow = tid >> 5;
    const int bCol = (tid & 31) << 2;
    const int gr = br + aRow;
    const int gc = bc + bCol;

    for (int k = k0; k < k1; k += 8) {
        float4 av = make_float4(0.f, 0.f, 0.f, 0.f);
        if (gr < M) av = *(const float4*)(A + (size_t)gr * K + k + aCol);
        As[aCol + 0][aRow] = av.x;
        As[aCol + 1][aRow] = av.y;
        As[aCol + 2][aRow] = av.z;
        As[aCol + 3][aRow] = av.w;
        float4 bv = make_float4(0.f, 0.f, 0.f, 0.f);
        if (gc < N) bv = *(const float4*)(B + (size_t)(k + bRow) * N + gc);
        *(float4*)(&Bs[bRow][bCol]) = bv;
        __syncthreads();
#pragma unroll
        for (int kk = 0; kk < 8; kk++) {
            float ra[8], rb[8];
#pragma unroll
            for (int i = 0; i < 8; i++) ra[i] = As[kk][tRow + i];
#pragma unroll
            for (int j = 0; j < 8; j++) rb[j] = Bs[kk][tCol + j];
#pragma unroll
            for (int i = 0; i < 8; i++)
#pragma unroll
                for (int j = 0; j < 8; j++)
                    acc[i][j] += ra[i] * rb[j];
        }
        __syncthreads();
    }
#pragma unroll
    for (int i = 0; i < 8; i++) {
        int r = br + tRow + i;
        if (r >= M) break;
#pragma unroll
        for (int j = 0; j < 8; j++) {
            int c = bc + tCol + j;
            if (c < N) {
                if (ATOMIC) atomicAdd(&C[(size_t)r * ldc + c], acc[i][j]);
                else        C[(size_t)r * ldc + c] = acc[i][j];
            }
        }
    }
}

// ---------------- final head ----------------
__global__ void final_head(const float* __restrict__ feat, const float* __restrict__ W5,
                           const float* __restrict__ b5, float* __restrict__ out)
{
    int b = blockIdx.x;
    int t = threadIdx.x;
    float a0 = 0.f, a1 = 0.f, a2 = 0.f, a3 = 0.f;
    const float* row = feat + (size_t)b * 1280;
    for (int k = t; k < 1280; k += 128) {
        float xv = row[k];
        const float* w = W5 + (size_t)k * 4;
        a0 += xv * w[0]; a1 += xv * w[1]; a2 += xv * w[2]; a3 += xv * w[3];
    }
    __shared__ float red[128][4];
    red[t][0] = a0; red[t][1] = a1; red[t][2] = a2; red[t][3] = a3;
    __syncthreads();
    for (int sft = 64; sft > 0; sft >>= 1) {
        if (t < sft) {
#pragma unroll
            for (int c = 0; c < 4; c++) red[t][c] += red[t + sft][c];
        }
        __syncthreads();
    }
    if (t == 0) {
        float v[4];
#pragma unroll
        for (int c = 0; c < 4; c++) v[c] = red[0][c] + b5[c];
        float m = fmaxf(fmaxf(v[0], v[1]), fmaxf(v[2], v[3]));
        float sum = 0.f;
#pragma unroll
        for (int c = 0; c < 4; c++) sum += expf(v[c] - m);
        float lse = m + logf(sum);
#pragma unroll
        for (int c = 0; c < 4; c++) out[(size_t)b * 4 + c] = v[c] - lse;
    }
}

// ---------------- host orchestration ----------------
static inline void gemm_ffma(const float* A, const float* B, float* C,
                             int M, int N, int K, int ldc, int splits)
{
    dim3 grid((N + 127) / 128, (M + 127) / 128, splits);
    if (splits > 1) {
        int chunk = ((K + splits - 1) / splits + 7) & ~7;
        sgemm128<true><<<grid, 256>>>(A, B, C, M, N, K, ldc, chunk);
    } else {
        sgemm128<false><<<grid, 256>>>(A, B, C, M, N, K, ldc, K);
    }
}

extern "C" void kernel_launch(void* const* d_in, const int* in_sizes, int n_in,
                              void* d_out, int out_size)
{
    const float* graph_x = (const float*)d_in[0];
    const float* data_x  = (const float*)d_in[2];
    const int*   ei      = (const int*)d_in[3];
    const int*   rei     = (const int*)d_in[4];
    const int*   batch   = (const int*)d_in[5];
    const int*   root    = (const int*)d_in[7];
    const float* W1  = (const float*)d_in[8];
    const float* b1  = (const float*)d_in[9];
    const float* Wc0 = (const float*)d_in[10];
    const float* bc0 = (const float*)d_in[11];
    const float* Wc1 = (const float*)d_in[12];
    const float* bc1 = (const float*)d_in[13];
    const float* Wc2 = (const float*)d_in[14];
    const float* bc2 = (const float*)d_in[15];
    const float* Wl1 = (const float*)d_in[16];
    const float* bl1 = (const float*)d_in[17];
    const float* Wl2 = (const float*)d_in[18];
    const float* bl2 = (const float*)d_in[19];
    const float* pa  = (const float*)d_in[20];
    const float* W5  = (const float*)d_in[21];
    const float* b5  = (const float*)d_in[22];
    float* out = (float*)d_out;

    const int E = in_sizes[3] / 2;

    float *h, *xa, *xb, *dg, *dr, *cat, *h2, *f5;
    int *degg, *degr, *st, *en, *rowg, *rowr, *curg, *curr;
    int2 *edgg, *edgr;
    uint16_t *wT;
    cudaGetSymbolAddress((void**)&h,    g_h);
    cudaGetSymbolAddress((void**)&xa,   g_xa);
    cudaGetSymbolAddress((void**)&xb,   g_xb);
    cudaGetSymbolAddress((void**)&dg,   g_dinv_g);
    cudaGetSymbolAddress((void**)&dr,   g_dinv_r);
    cudaGetSymbolAddress((void**)&degg, g_deg_g);
    cudaGetSymbolAddress((void**)&degr, g_deg_r);
    cudaGetSymbolAddress((void**)&st,   g_start);
    cudaGetSymbolAddress((void**)&en,   g_end);
    cudaGetSymbolAddress((void**)&cat,  g_cat);
    cudaGetSymbolAddress((void**)&h2,   g_h2);
    cudaGetSymbolAddress((void**)&f5,   g_f5);
    cudaGetSymbolAddress((void**)&wT,   g_wT);
    cudaGetSymbolAddress((void**)&rowg, g_rowg);
    cudaGetSymbolAddress((void**)&rowr, g_rowr);
    cudaGetSymbolAddress((void**)&curg, g_curg);
    cudaGetSymbolAddress((void**)&curr, g_curr);
    cudaGetSymbolAddress((void**)&edgg, g_edgg);
    cudaGetSymbolAddress((void**)&edgr, g_edgr);

    cudaFuncSetAttribute(gcn_gemm_mma<false>, cudaFuncAttributeMaxDynamicSharedMemorySize, MMA_SMEM);
    cudaFuncSetAttribute(gcn_gemm_mma<true>,  cudaFuncAttributeMaxDynamicSharedMemorySize, MMA_SMEM);

    const int NT = 256;
    const int gemmGrid = (N_NODES + BM - 1) / BM;
    const int gatherGrid = (N_NODES + 3) / 4;

    // ---- degrees + dinv + segment bounds + CSR; zero cat for fused segment sums ----
    zero_i<<<128, NT>>>(degg, N_NODES);
    zero_i<<<128, NT>>>(degr, N_NODES);
    zero_f<<<256, NT>>>(cat, B_GR * 2 * RAWF);
    deg_kernel<<<(E + NT - 1) / NT, NT>>>(ei + E, degg, E);
    deg_kernel<<<(E + NT - 1) / NT, NT>>>(rei + E, degr, E);
    dinv_kernel<<<(N_NODES + NT - 1) / NT, NT>>>(degg, dg, N_NODES);
    dinv_kernel<<<(N_NODES + NT - 1) / NT, NT>>>(degr, dr, N_NODES);
    init_bounds<<<1, 128>>>(st, en);
    bounds_kernel<<<(N_NODES + NT - 1) / NT, NT>>>(batch, st, en, N_NODES);
    scan_kernel<<<1, 1024>>>(degg, rowg, curg, N_NODES);
    scan_kernel<<<1, 1024>>>(degr, rowr, curr, N_NODES);
    csr_fill<<<(E + NT - 1) / NT, NT>>>(ei, ei + E, dg, curg, edgg, E);
    csr_fill<<<(E + NT - 1) / NT, NT>>>(rei, rei + E, dr, curr, edgr, E);

    // ---- branch 1: GCN(graph_x, W1) -> gather -> max pool (bias+relu fused) ----
    wconv<<<(FIN * 256 + NT - 1) / NT, NT>>>(W1, FIN, wT);
    gcn_gemm_mma<false><<<gemmGrid, NTG, MMA_SMEM>>>(graph_x, wT, h, nullptr, nullptr, nullptr, N_NODES, FIN);
    gcn_gather<<<gatherGrid, 256>>>((const float4*)h, rowg, edgg, dg, (float4*)xa);
    pool_max_br<<<B_GR, HDIM>>>(xa, b1, st, en, f5 + 1024, 1280);

    // ---- branch 3: 3 GCN layers on raw graph (layer 0 also fuses data_x segment sums) ----
    wconv<<<(RAWF * 256 + NT - 1) / NT, NT>>>(Wc0, RAWF, wT);
    gcn_gemm_mma<true><<<gemmGrid, NTG, MMA_SMEM>>>(data_x, wT, h, nullptr, batch, cat, N_NODES, RAWF);
    gcn_gather<<<gatherGrid, 256>>>((const float4*)h, rowr, edgr, dr, (float4*)xa);
    pool_mean_br<<<B_GR, HDIM>>>(xa, bc0, st, en, f5 + 0, 1280);

    wconv<<<(HDIM * 256 + NT - 1) / NT, NT>>>(Wc1, HDIM, wT);
    gcn_gemm_mma<false><<<gemmGrid, NTG, MMA_SMEM>>>(xa, wT, h, bc0, nullptr, nullptr, N_NODES, HDIM);
    gcn_gather<<<gatherGrid, 256>>>((const float4*)h, rowr, edgr, dr, (float4*)xb);
    pool_mean_br<<<B_GR, HDIM>>>(xb, bc1, st, en, f5 + 256, 1280);

    wconv<<<(HDIM * 256 + NT - 1) / NT, NT>>>(Wc2, HDIM, wT);
    gcn_gemm_mma<false><<<gemmGrid, NTG, MMA_SMEM>>>(xb, wT, h, bc1, nullptr, nullptr, N_NODES, HDIM);
    gcn_gather<<<gatherGrid, 256>>>((const float4*)h, rowr, edgr, dr, (float4*)xa);
    pool_mean_br<<<B_GR, HDIM>>>(xa, bc2, st, en, f5 + 512, 1280);

    // ---- branch 2: [segment_mean(data_x) | data_x[root]] -> MLP w/ PReLU ----
    mean_div<<<dim3((RAWF + NT - 1) / NT, B_GR), NT>>>(cat, st, en);
    gather_root<<<dim3((RAWF + NT - 1) / NT, B_GR), NT>>>(data_x, root, cat + RAWF, 2 * RAWF);
    zero_f<<<64, NT>>>(h2, B_GR * 512);
    gemm_ffma(cat, Wl1, h2, B_GR, 512, 2 * RAWF, 512, 25);
    prelu_bias<<<(B_GR * 512 + NT - 1) / NT, NT>>>(h2, bl1, pa, h2, B_GR, 512, 512);
    {
        float* nx = f5 + B_GR * 1280;  // unused? no — use h as scratch (20000*256 floats, only 128*256 needed)
        nx = h;                        // h fully consumed by last gather above
        zero_f<<<64, NT>>>(nx, B_GR * HDIM);
        gemm_ffma(h2, Wl2, nx, B_GR, HDIM, 512, HDIM, 8);
        prelu_bias<<<(B_GR * HDIM + NT - 1) / NT, NT>>>(nx, bl2, pa, f5 + 768, B_GR, HDIM, 1280);
    }

    // ---- head ----
    final_head<<<B_GR, 128>>>(f5, W5, b5, out);
}